// round 2
// baseline (speedup 1.0000x reference)
#include <cuda_runtime.h>
#include <cstddef>

#define BB 2
#define SEQ 4096
#define DMODEL 768
#define NHEADS 12
#define HDIM 64
#define MTOT (BB * SEQ)   // 8192

// Scratch (alloc-free rule: __device__ globals)
__device__ float g_q[MTOT * DMODEL];
__device__ float g_k[MTOT * DMODEL];
__device__ float g_v[MTOT * DMODEL];
__device__ float g_ctx[MTOT * DMODEL];

// ---------------------------------------------------------------------------
// SGEMM: C[M,N] = A[M,K] @ B[K,N] (+bias). Row-major everywhere.
// BM=BN=64, BK=16, 64 threads, each thread 8x8 microtile.
// ---------------------------------------------------------------------------
#define GBM 64
#define GBN 64
#define GBK 16

__global__ __launch_bounds__(64) void sgemm_kernel(
    const float* __restrict__ A, const float* __restrict__ B,
    const float* __restrict__ bias, float* __restrict__ C,
    int M, int N, int K)
{
    __shared__ float As[GBK][GBM];
    __shared__ float Bs[GBK][GBN];

    const int t  = threadIdx.x;        // 0..63
    const int tx = t & 7;              // col group
    const int ty = t >> 3;             // row group
    const int row0 = blockIdx.y * GBM;
    const int col0 = blockIdx.x * GBN;

    float acc[8][8];
#pragma unroll
    for (int i = 0; i < 8; i++)
#pragma unroll
        for (int j = 0; j < 8; j++) acc[i][j] = 0.0f;

    for (int k0 = 0; k0 < K; k0 += GBK) {
        // Load A tile (64 rows x 16 cols): thread t loads its own row (4 float4)
        const float* Arow = A + (size_t)(row0 + t) * K + k0;
#pragma unroll
        for (int c = 0; c < 4; c++) {
            float4 v = *(const float4*)(Arow + c * 4);
            As[c * 4 + 0][t] = v.x;
            As[c * 4 + 1][t] = v.y;
            As[c * 4 + 2][t] = v.z;
            As[c * 4 + 3][t] = v.w;
        }
        // Load B tile (16 rows x 64 cols): 4 float4 per thread, coalesced
#pragma unroll
        for (int i = 0; i < 4; i++) {
            int f  = t + 64 * i;
            int r  = f >> 4;
            int c4 = f & 15;
            float4 v = *(const float4*)(B + (size_t)(k0 + r) * N + col0 + c4 * 4);
            *(float4*)&Bs[r][c4 * 4] = v;
        }
        __syncthreads();

#pragma unroll
        for (int k = 0; k < GBK; k++) {
            float a[8], b[8];
#pragma unroll
            for (int i = 0; i < 8; i += 4) {
                float4 v = *(const float4*)&As[k][ty * 8 + i];
                a[i] = v.x; a[i + 1] = v.y; a[i + 2] = v.z; a[i + 3] = v.w;
            }
#pragma unroll
            for (int j = 0; j < 8; j += 4) {
                float4 v = *(const float4*)&Bs[k][tx * 8 + j];
                b[j] = v.x; b[j + 1] = v.y; b[j + 2] = v.z; b[j + 3] = v.w;
            }
#pragma unroll
            for (int i = 0; i < 8; i++)
#pragma unroll
                for (int j = 0; j < 8; j++)
                    acc[i][j] = fmaf(a[i], b[j], acc[i][j]);
        }
        __syncthreads();
    }

    // Write out (+bias)
#pragma unroll
    for (int i = 0; i < 8; i++) {
        float* Crow = C + (size_t)(row0 + ty * 8 + i) * N + col0 + tx * 8;
        float bv[8];
#pragma unroll
        for (int j = 0; j < 8; j++)
            bv[j] = acc[i][j] + (bias ? bias[col0 + tx * 8 + j] : 0.0f);
        *(float4*)(Crow + 0) = make_float4(bv[0], bv[1], bv[2], bv[3]);
        *(float4*)(Crow + 4) = make_float4(bv[4], bv[5], bv[6], bv[7]);
    }
}

// ---------------------------------------------------------------------------
// Flash attention, fp32, causal. One block = one (batch, head, 64-row Q tile).
// 64 threads; thread i owns Q row i of the tile (q + acc fully in registers).
// smem = 48KB exactly: K tile 16KB + V tile 16KB + swizzled score rows 16KB.
// ---------------------------------------------------------------------------
__global__ __launch_bounds__(64) void attn_kernel(
    const float* __restrict__ Q, const float* __restrict__ K,
    const float* __restrict__ V, float* __restrict__ O)
{
    __shared__ float Ks[64][64];
    __shared__ float Vs[64][64];
    __shared__ float Ss[64 * 64];   // row t, column j stored at j ^ (t&31)

    const int t  = threadIdx.x;      // 0..63
    const int qt = blockIdx.x;       // q tile
    const int h  = blockIdx.y;
    const int b  = blockIdx.z;

    const int qtok = qt * 64 + t;
    const float scale = 0.125f;      // 1/sqrt(64)

    const float* qptr = Q + ((size_t)(b * SEQ + qtok)) * DMODEL + h * HDIM;
    float q[64];
#pragma unroll
    for (int i = 0; i < 16; i++) {
        float4 v = *(const float4*)(qptr + i * 4);
        q[i * 4 + 0] = v.x * scale;
        q[i * 4 + 1] = v.y * scale;
        q[i * 4 + 2] = v.z * scale;
        q[i * 4 + 3] = v.w * scale;
    }

    float mrun = -1e30f;
    float lrun = 0.0f;
    float acc[64];
#pragma unroll
    for (int d = 0; d < 64; d++) acc[d] = 0.0f;

    const int swz = t & 31;

    for (int kt = 0; kt <= qt; kt++) {
        // Cooperative K/V tile load (64 tokens x 64 dims each)
#pragma unroll
        for (int i = 0; i < 16; i++) {
            int f  = t + 64 * i;
            int r  = f >> 4;
            int c4 = f & 15;
            size_t base = ((size_t)(b * SEQ + kt * 64 + r)) * DMODEL + h * HDIM + c4 * 4;
            *(float4*)&Ks[r][c4 * 4] = *(const float4*)(K + base);
            *(float4*)&Vs[r][c4 * 4] = *(const float4*)(V + base);
        }
        __syncthreads();

        const bool diag = (kt == qt);
        float tmax = -1e30f;

        // Pass 1: scores for my row, tile max
        for (int j = 0; j < 64; j++) {
            float s = 0.0f;
#pragma unroll
            for (int d = 0; d < 64; d += 4) {
                float4 kv = *(const float4*)&Ks[j][d];
                s = fmaf(q[d + 0], kv.x, s);
                s = fmaf(q[d + 1], kv.y, s);
                s = fmaf(q[d + 2], kv.z, s);
                s = fmaf(q[d + 3], kv.w, s);
            }
            if (diag && (kt * 64 + j) > qtok) s = -1e30f;
            Ss[t * 64 + (j ^ swz)] = s;
            tmax = fmaxf(tmax, s);
        }

        const float mnew  = fmaxf(mrun, tmax);
        const float alpha = __expf(mrun - mnew);
        lrun *= alpha;
#pragma unroll
        for (int d = 0; d < 64; d++) acc[d] *= alpha;

        // Pass 2: p = exp(s - mnew), acc += p * V
        for (int j = 0; j < 64; j++) {
            float p = __expf(Ss[t * 64 + (j ^ swz)] - mnew);
            lrun += p;
#pragma unroll
            for (int d = 0; d < 64; d += 4) {
                float4 vv = *(const float4*)&Vs[j][d];
                acc[d + 0] = fmaf(p, vv.x, acc[d + 0]);
                acc[d + 1] = fmaf(p, vv.y, acc[d + 1]);
                acc[d + 2] = fmaf(p, vv.z, acc[d + 2]);
                acc[d + 3] = fmaf(p, vv.w, acc[d + 3]);
            }
        }
        mrun = mnew;
        __syncthreads();
    }

    const float inv = 1.0f / lrun;
    float* optr = O + ((size_t)(b * SEQ + qtok)) * DMODEL + h * HDIM;
#pragma unroll
    for (int d = 0; d < 64; d += 4) {
        *(float4*)(optr + d) = make_float4(acc[d] * inv, acc[d + 1] * inv,
                                           acc[d + 2] * inv, acc[d + 3] * inv);
    }
}

// ---------------------------------------------------------------------------
extern "C" void kernel_launch(void* const* d_in, const int* in_sizes, int n_in,
                              void* d_out, int out_size)
{
    (void)in_sizes; (void)n_in; (void)out_size;
    const float* x  = (const float*)d_in[0];
    const float* wq = (const float*)d_in[1];
    const float* wk = (const float*)d_in[2];
    const float* wv = (const float*)d_in[3];
    const float* wo = (const float*)d_in[4];
    const float* bo = (const float*)d_in[5];
    float* out = (float*)d_out;

    float *qp, *kp, *vp, *cp;
    cudaGetSymbolAddress((void**)&qp, g_q);
    cudaGetSymbolAddress((void**)&kp, g_k);
    cudaGetSymbolAddress((void**)&vp, g_v);
    cudaGetSymbolAddress((void**)&cp, g_ctx);

    dim3 gemm_grid(DMODEL / GBN, MTOT / GBM);  // (12, 128)
    sgemm_kernel<<<gemm_grid, 64>>>(x, wq, nullptr, qp, MTOT, DMODEL, DMODEL);
    sgemm_kernel<<<gemm_grid, 64>>>(x, wk, nullptr, kp, MTOT, DMODEL, DMODEL);
    sgemm_kernel<<<gemm_grid, 64>>>(x, wv, nullptr, vp, MTOT, DMODEL, DMODEL);

    dim3 attn_grid(SEQ / 64, NHEADS, BB);      // (64, 12, 2)
    attn_kernel<<<attn_grid, 64>>>(qp, kp, vp, cp);

    sgemm_kernel<<<gemm_grid, 64>>>(cp, wo, bo, out, MTOT, DMODEL, DMODEL);
}

// round 3
// speedup vs baseline: 3.8890x; 3.8890x over previous
#include <cuda_runtime.h>
#include <cstddef>

#define BB 2
#define SEQ 4096
#define DMODEL 768
#define NHEADS 12
#define HDIM 64
#define MTOT (BB * SEQ)   // 8192

// Scratch (alloc-free rule: __device__ globals)
__device__ float g_q[MTOT * DMODEL];
__device__ float g_k[MTOT * DMODEL];
__device__ float g_v[MTOT * DMODEL];
__device__ float g_ctx[MTOT * DMODEL];

// ---------------------------------------------------------------------------
// helpers
// ---------------------------------------------------------------------------
__device__ __forceinline__ unsigned f2tf(float f) {
    unsigned u;
    asm("cvt.rna.tf32.f32 %0, %1;" : "=r"(u) : "f"(f));
    return u;
}
__device__ __forceinline__ float ex2f(float x) {
    float y;
    asm("ex2.approx.f32 %0, %1;" : "=f"(y) : "f"(x));
    return y;
}
__device__ __forceinline__ void mma8(float c[4], const unsigned a[4], const unsigned b[2]) {
    asm volatile(
        "mma.sync.aligned.m16n8k8.row.col.f32.tf32.tf32.f32 "
        "{%0,%1,%2,%3}, {%4,%5,%6,%7}, {%8,%9}, {%0,%1,%2,%3};\n"
        : "+f"(c[0]), "+f"(c[1]), "+f"(c[2]), "+f"(c[3])
        : "r"(a[0]), "r"(a[1]), "r"(a[2]), "r"(a[3]), "r"(b[0]), "r"(b[1]));
}

// ---------------------------------------------------------------------------
// tf32 GEMM: C[M,N] = A[M,K] @ B[K,N] (+bias). 256 threads, tile 128x64x32.
// 8 warps = 4(m) x 2(n), each warp 32x32 = 2x4 m16n8 tiles.
// Smem pads: A stride 36 words (frag banks 4g+t, conflict-free),
//            B stride 72 words (frag banks 8t+g, conflict-free).
// ---------------------------------------------------------------------------
#define TBM 128
#define TBN 64
#define TBK 32
#define ASTR 36
#define BSTR 72

__global__ __launch_bounds__(256) void gemm_tf32(
    const float* __restrict__ A, const float* __restrict__ B,
    const float* __restrict__ bias, float* __restrict__ C,
    int M, int N, int K)
{
    __shared__ __align__(16) unsigned As[TBM * ASTR];
    __shared__ __align__(16) unsigned Bs[TBK * BSTR];

    const int tid  = threadIdx.x;
    const int lane = tid & 31;
    const int w    = tid >> 5;
    const int g    = lane >> 2;
    const int t    = lane & 3;
    const int wm   = (w & 3) * 32;
    const int wn   = (w >> 2) * 32;
    const int row0 = blockIdx.y * TBM;
    const int col0 = blockIdx.x * TBN;

    float c[2][4][4];
#pragma unroll
    for (int mi = 0; mi < 2; mi++)
#pragma unroll
        for (int ni = 0; ni < 4; ni++)
#pragma unroll
            for (int r = 0; r < 4; r++) c[mi][ni][r] = 0.0f;

    const int nk = K / TBK;
    float4 ra[4], rb[2];

    // prologue load
#pragma unroll
    for (int i = 0; i < 4; i++) {
        int idx = tid + 256 * i, r = idx >> 3, c4 = idx & 7;
        ra[i] = *(const float4*)(A + (size_t)(row0 + r) * K + c4 * 4);
    }
#pragma unroll
    for (int i = 0; i < 2; i++) {
        int idx = tid + 256 * i, r = idx >> 4, c4 = idx & 15;
        rb[i] = *(const float4*)(B + (size_t)r * N + col0 + c4 * 4);
    }
    // store tile 0
#pragma unroll
    for (int i = 0; i < 4; i++) {
        int idx = tid + 256 * i, r = idx >> 3, c4 = idx & 7;
        uint4 u = make_uint4(f2tf(ra[i].x), f2tf(ra[i].y), f2tf(ra[i].z), f2tf(ra[i].w));
        *(uint4*)&As[r * ASTR + c4 * 4] = u;
    }
#pragma unroll
    for (int i = 0; i < 2; i++) {
        int idx = tid + 256 * i, r = idx >> 4, c4 = idx & 15;
        uint4 u = make_uint4(f2tf(rb[i].x), f2tf(rb[i].y), f2tf(rb[i].z), f2tf(rb[i].w));
        *(uint4*)&Bs[r * BSTR + c4 * 4] = u;
    }
    __syncthreads();

    for (int kt = 0; kt < nk; kt++) {
        if (kt + 1 < nk) {
            int k0 = (kt + 1) * TBK;
#pragma unroll
            for (int i = 0; i < 4; i++) {
                int idx = tid + 256 * i, r = idx >> 3, c4 = idx & 7;
                ra[i] = *(const float4*)(A + (size_t)(row0 + r) * K + k0 + c4 * 4);
            }
#pragma unroll
            for (int i = 0; i < 2; i++) {
                int idx = tid + 256 * i, r = idx >> 4, c4 = idx & 15;
                rb[i] = *(const float4*)(B + (size_t)(k0 + r) * N + col0 + c4 * 4);
            }
        }
        // compute current tile
#pragma unroll
        for (int kp = 0; kp < 4; kp++) {
            unsigned af[2][4], bf[4][2];
#pragma unroll
            for (int mi = 0; mi < 2; mi++) {
                int r0 = (wm + mi * 16 + g) * ASTR + kp * 8 + t;
                int r1 = (wm + mi * 16 + g + 8) * ASTR + kp * 8 + t;
                af[mi][0] = As[r0];
                af[mi][1] = As[r1];
                af[mi][2] = As[r0 + 4];
                af[mi][3] = As[r1 + 4];
            }
#pragma unroll
            for (int ni = 0; ni < 4; ni++) {
                bf[ni][0] = Bs[(kp * 8 + t) * BSTR + wn + ni * 8 + g];
                bf[ni][1] = Bs[(kp * 8 + t + 4) * BSTR + wn + ni * 8 + g];
            }
#pragma unroll
            for (int mi = 0; mi < 2; mi++)
#pragma unroll
                for (int ni = 0; ni < 4; ni++)
                    mma8(c[mi][ni], af[mi], bf[ni]);
        }
        __syncthreads();
        if (kt + 1 < nk) {
#pragma unroll
            for (int i = 0; i < 4; i++) {
                int idx = tid + 256 * i, r = idx >> 3, c4 = idx & 7;
                uint4 u = make_uint4(f2tf(ra[i].x), f2tf(ra[i].y), f2tf(ra[i].z), f2tf(ra[i].w));
                *(uint4*)&As[r * ASTR + c4 * 4] = u;
            }
#pragma unroll
            for (int i = 0; i < 2; i++) {
                int idx = tid + 256 * i, r = idx >> 4, c4 = idx & 15;
                uint4 u = make_uint4(f2tf(rb[i].x), f2tf(rb[i].y), f2tf(rb[i].z), f2tf(rb[i].w));
                *(uint4*)&Bs[r * BSTR + c4 * 4] = u;
            }
            __syncthreads();
        }
    }

    // epilogue
#pragma unroll
    for (int ni = 0; ni < 4; ni++) {
        int col = col0 + wn + ni * 8 + 2 * t;
        float2 bv = make_float2(0.0f, 0.0f);
        if (bias) bv = *(const float2*)(bias + col);
#pragma unroll
        for (int mi = 0; mi < 2; mi++) {
            int r0 = row0 + wm + mi * 16 + g;
            *(float2*)(C + (size_t)r0 * N + col) =
                make_float2(c[mi][ni][0] + bv.x, c[mi][ni][1] + bv.y);
            *(float2*)(C + (size_t)(r0 + 8) * N + col) =
                make_float2(c[mi][ni][2] + bv.x, c[mi][ni][3] + bv.y);
        }
    }
}

// ---------------------------------------------------------------------------
// Flash attention, tf32 mma, causal. Block = (b, h, 64-row Q tile), 128 thr.
// Warp w owns 16 Q rows. QK^T and PV both m16n8k8 tf32; P staged through smem
// (aliased with K tile). Softmax in fp32 regs, ex2-based, scale folded into Q.
// ---------------------------------------------------------------------------
#define KSTR 68   // K/P tile stride (banks: B-frag 4g+t, A-frag 4g+t — clean)
#define VSTR 72   // V tile stride  (banks: B-frag 8t+g — clean)

__global__ __launch_bounds__(128) void attn_tf32(
    const float* __restrict__ Q, const float* __restrict__ K,
    const float* __restrict__ V, float* __restrict__ O)
{
    __shared__ __align__(16) unsigned KPs[64 * KSTR]; // K tile, then P staging
    __shared__ __align__(16) unsigned Vs[64 * VSTR];  // Q staging, then V tile

    const int tid  = threadIdx.x;
    const int lane = tid & 31;
    const int w    = tid >> 5;
    const int g    = lane >> 2;
    const int t    = lane & 3;
    const int qt   = blockIdx.x;
    const int h    = blockIdx.y;
    const int b    = blockIdx.z;

    const float qscale = 0.125f * 1.4426950408889634f; // 1/sqrt(64) * log2(e)
    const size_t baseQ = ((size_t)(b * SEQ + qt * 64)) * DMODEL + h * HDIM;

    // stage Q (scaled, tf32) through Vs, pull fragments to registers
#pragma unroll
    for (int i = 0; i < 8; i++) {
        int idx = tid + 128 * i, r = idx >> 4, c4 = idx & 15;
        float4 v = *(const float4*)(Q + baseQ + (size_t)r * DMODEL + c4 * 4);
        uint4 u = make_uint4(f2tf(v.x * qscale), f2tf(v.y * qscale),
                             f2tf(v.z * qscale), f2tf(v.w * qscale));
        *(uint4*)&Vs[r * VSTR + c4 * 4] = u;
    }
    __syncthreads();
    unsigned aq[8][4];
#pragma unroll
    for (int kp = 0; kp < 8; kp++) {
        int r0 = (w * 16 + g) * VSTR + kp * 8 + t;
        int r1 = (w * 16 + g + 8) * VSTR + kp * 8 + t;
        aq[kp][0] = Vs[r0];
        aq[kp][1] = Vs[r1];
        aq[kp][2] = Vs[r0 + 4];
        aq[kp][3] = Vs[r1 + 4];
    }
    __syncthreads();

    float co[8][4];
#pragma unroll
    for (int ni = 0; ni < 8; ni++)
#pragma unroll
        for (int r = 0; r < 4; r++) co[ni][r] = 0.0f;
    float m0 = -1e30f, m1 = -1e30f, l0 = 0.0f, l1 = 0.0f;

    for (int kt = 0; kt <= qt; kt++) {
        // cooperative K/V tile load (tf32-converted)
#pragma unroll
        for (int i = 0; i < 8; i++) {
            int idx = tid + 128 * i, r = idx >> 4, c4 = idx & 15;
            size_t base = ((size_t)(b * SEQ + kt * 64 + r)) * DMODEL + h * HDIM + c4 * 4;
            float4 kv = *(const float4*)(K + base);
            float4 vv = *(const float4*)(V + base);
            *(uint4*)&KPs[r * KSTR + c4 * 4] =
                make_uint4(f2tf(kv.x), f2tf(kv.y), f2tf(kv.z), f2tf(kv.w));
            *(uint4*)&Vs[r * VSTR + c4 * 4] =
                make_uint4(f2tf(vv.x), f2tf(vv.y), f2tf(vv.z), f2tf(vv.w));
        }
        __syncthreads();

        // S = Q K^T  (fragments accumulate over 8 k-phases)
        float cs[8][4];
#pragma unroll
        for (int ni = 0; ni < 8; ni++)
#pragma unroll
            for (int r = 0; r < 4; r++) cs[ni][r] = 0.0f;
#pragma unroll
        for (int kp = 0; kp < 8; kp++) {
#pragma unroll
            for (int ni = 0; ni < 8; ni++) {
                unsigned bf[2];
                int rr = (ni * 8 + g) * KSTR + kp * 8 + t;
                bf[0] = KPs[rr];
                bf[1] = KPs[rr + 4];
                mma8(cs[ni], aq[kp], bf);
            }
        }

        // causal mask (diagonal tile only; indices tile-local since kt==qt)
        if (kt == qt) {
#pragma unroll
            for (int ni = 0; ni < 8; ni++) {
                int colb = ni * 8 + 2 * t;
                int rowa = w * 16 + g;
                if (colb > rowa)         cs[ni][0] = -1e30f;
                if (colb + 1 > rowa)     cs[ni][1] = -1e30f;
                if (colb > rowa + 8)     cs[ni][2] = -1e30f;
                if (colb + 1 > rowa + 8) cs[ni][3] = -1e30f;
            }
        }

        // online softmax (base-2 domain)
        float tm0 = -1e30f, tm1 = -1e30f;
#pragma unroll
        for (int ni = 0; ni < 8; ni++) {
            tm0 = fmaxf(tm0, fmaxf(cs[ni][0], cs[ni][1]));
            tm1 = fmaxf(tm1, fmaxf(cs[ni][2], cs[ni][3]));
        }
        tm0 = fmaxf(tm0, __shfl_xor_sync(0xffffffffu, tm0, 1));
        tm0 = fmaxf(tm0, __shfl_xor_sync(0xffffffffu, tm0, 2));
        tm1 = fmaxf(tm1, __shfl_xor_sync(0xffffffffu, tm1, 1));
        tm1 = fmaxf(tm1, __shfl_xor_sync(0xffffffffu, tm1, 2));

        float mn0 = fmaxf(m0, tm0), mn1 = fmaxf(m1, tm1);
        float al0 = ex2f(m0 - mn0), al1 = ex2f(m1 - mn1);
        float s0 = 0.0f, s1 = 0.0f;
#pragma unroll
        for (int ni = 0; ni < 8; ni++) {
            cs[ni][0] = ex2f(cs[ni][0] - mn0); s0 += cs[ni][0];
            cs[ni][1] = ex2f(cs[ni][1] - mn0); s0 += cs[ni][1];
            cs[ni][2] = ex2f(cs[ni][2] - mn1); s1 += cs[ni][2];
            cs[ni][3] = ex2f(cs[ni][3] - mn1); s1 += cs[ni][3];
        }
        s0 += __shfl_xor_sync(0xffffffffu, s0, 1);
        s0 += __shfl_xor_sync(0xffffffffu, s0, 2);
        s1 += __shfl_xor_sync(0xffffffffu, s1, 1);
        s1 += __shfl_xor_sync(0xffffffffu, s1, 2);
        l0 = l0 * al0 + s0;
        l1 = l1 * al1 + s1;
        m0 = mn0; m1 = mn1;
#pragma unroll
        for (int ni = 0; ni < 8; ni++) {
            co[ni][0] *= al0; co[ni][1] *= al0;
            co[ni][2] *= al1; co[ni][3] *= al1;
        }

        __syncthreads();   // everyone done reading K tile before P overwrites it

        // stage P (tf32) into KPs; each warp touches only its own 16 rows
#pragma unroll
        for (int ni = 0; ni < 8; ni++) {
            unsigned* p0 = &KPs[(w * 16 + g) * KSTR + ni * 8 + 2 * t];
            p0[0] = f2tf(cs[ni][0]);
            p0[1] = f2tf(cs[ni][1]);
            unsigned* p1 = &KPs[(w * 16 + g + 8) * KSTR + ni * 8 + 2 * t];
            p1[0] = f2tf(cs[ni][2]);
            p1[1] = f2tf(cs[ni][3]);
        }
        __syncwarp();

        // O += P V
#pragma unroll
        for (int kp = 0; kp < 8; kp++) {
            unsigned ap[4];
            int r0 = (w * 16 + g) * KSTR + kp * 8 + t;
            int r1 = (w * 16 + g + 8) * KSTR + kp * 8 + t;
            ap[0] = KPs[r0];
            ap[1] = KPs[r1];
            ap[2] = KPs[r0 + 4];
            ap[3] = KPs[r1 + 4];
#pragma unroll
            for (int ni = 0; ni < 8; ni++) {
                unsigned bf[2];
                bf[0] = Vs[(kp * 8 + t) * VSTR + ni * 8 + g];
                bf[1] = Vs[(kp * 8 + t + 4) * VSTR + ni * 8 + g];
                mma8(co[ni], ap, bf);
            }
        }
        __syncthreads();   // before next iter's tile load overwrites KPs/Vs
    }

    const float i0 = 1.0f / l0, i1 = 1.0f / l1;
#pragma unroll
    for (int ni = 0; ni < 8; ni++) {
        size_t r0 = ((size_t)(b * SEQ + qt * 64 + w * 16 + g)) * DMODEL + h * HDIM + ni * 8 + 2 * t;
        *(float2*)(O + r0) = make_float2(co[ni][0] * i0, co[ni][1] * i0);
        *(float2*)(O + r0 + (size_t)8 * DMODEL) = make_float2(co[ni][2] * i1, co[ni][3] * i1);
    }
}

// ---------------------------------------------------------------------------
extern "C" void kernel_launch(void* const* d_in, const int* in_sizes, int n_in,
                              void* d_out, int out_size)
{
    (void)in_sizes; (void)n_in; (void)out_size;
    const float* x  = (const float*)d_in[0];
    const float* wq = (const float*)d_in[1];
    const float* wk = (const float*)d_in[2];
    const float* wv = (const float*)d_in[3];
    const float* wo = (const float*)d_in[4];
    const float* bo = (const float*)d_in[5];
    float* out = (float*)d_out;

    float *qp, *kp, *vp, *cp;
    cudaGetSymbolAddress((void**)&qp, g_q);
    cudaGetSymbolAddress((void**)&kp, g_k);
    cudaGetSymbolAddress((void**)&vp, g_v);
    cudaGetSymbolAddress((void**)&cp, g_ctx);

    dim3 gemm_grid(DMODEL / TBN, MTOT / TBM);   // (12, 64)
    gemm_tf32<<<gemm_grid, 256>>>(x, wq, nullptr, qp, MTOT, DMODEL, DMODEL);
    gemm_tf32<<<gemm_grid, 256>>>(x, wk, nullptr, kp, MTOT, DMODEL, DMODEL);
    gemm_tf32<<<gemm_grid, 256>>>(x, wv, nullptr, vp, MTOT, DMODEL, DMODEL);

    dim3 attn_grid(SEQ / 64, NHEADS, BB);       // (64, 12, 2)
    attn_tf32<<<attn_grid, 128>>>(qp, kp, vp, cp);

    gemm_tf32<<<gemm_grid, 256>>>(cp, wo, bo, out, MTOT, DMODEL, DMODEL);
}

// round 5
// speedup vs baseline: 4.5143x; 1.1608x over previous
#include <cuda_runtime.h>
#include <cstddef>
#include <cstdint>

#define BB 2
#define SEQ 4096
#define DMODEL 768
#define NHEADS 12
#define HDIM 64
#define MTOT (BB * SEQ)   // 8192

// Scratch (alloc-free rule: __device__ globals)
__device__ float g_xt[MTOT * DMODEL];            // x, tf32-rounded
__device__ float g_wt[4 * DMODEL * DMODEL];      // wq,wk,wv,wo tf32-rounded
__device__ float g_q[MTOT * DMODEL];
__device__ float g_k[MTOT * DMODEL];
__device__ float g_v[MTOT * DMODEL];
__device__ float g_ctx[MTOT * DMODEL];

// ---------------------------------------------------------------------------
// helpers
// ---------------------------------------------------------------------------
__device__ __forceinline__ unsigned f2tf(float f) {
    unsigned u;
    asm("cvt.rna.tf32.f32 %0, %1;" : "=r"(u) : "f"(f));
    return u;
}
__device__ __forceinline__ float ex2f(float x) {
    float y;
    asm("ex2.approx.f32 %0, %1;" : "=f"(y) : "f"(x));
    return y;
}
__device__ __forceinline__ void mma8(float c[4], const unsigned a[4], const unsigned b[2]) {
    asm volatile(
        "mma.sync.aligned.m16n8k8.row.col.f32.tf32.tf32.f32 "
        "{%0,%1,%2,%3}, {%4,%5,%6,%7}, {%8,%9}, {%0,%1,%2,%3};\n"
        : "+f"(c[0]), "+f"(c[1]), "+f"(c[2]), "+f"(c[3])
        : "r"(a[0]), "r"(a[1]), "r"(a[2]), "r"(a[3]), "r"(b[0]), "r"(b[1]));
}
__device__ __forceinline__ void cp16(uint32_t dst, const void* src) {
    asm volatile("cp.async.cg.shared.global [%0], [%1], 16;\n" :: "r"(dst), "l"(src));
}
#define CP_COMMIT() asm volatile("cp.async.commit_group;\n" ::: "memory")
#define CP_WAIT0()  asm volatile("cp.async.wait_group 0;\n" ::: "memory")

// ---------------------------------------------------------------------------
// prep: fp32 -> tf32-rounded fp32 (elementwise, float4)
// ---------------------------------------------------------------------------
__global__ void prep_tf32(const float* __restrict__ src, float* __restrict__ dst, int n4)
{
    int i = blockIdx.x * blockDim.x + threadIdx.x;
    if (i >= n4) return;
    float4 v = ((const float4*)src)[i];
    v.x = __uint_as_float(f2tf(v.x));
    v.y = __uint_as_float(f2tf(v.y));
    v.z = __uint_as_float(f2tf(v.z));
    v.w = __uint_as_float(f2tf(v.w));
    ((float4*)dst)[i] = v;
}

// ---------------------------------------------------------------------------
// tf32 GEMM: C = A@B (*outscale, +bias, optional tf32-round of output).
// Inputs already tf32 bit patterns. 256 thr, tile 128x64x32, cp.async 2-stage.
// ---------------------------------------------------------------------------
#define TBM 128
#define TBN 64
#define TBK 32
#define ASTR 36
#define BSTR 72
#define GBUF (TBM * ASTR + TBK * BSTR)   // 6912 words per stage
#define GEMM_SMEM (2 * GBUF * 4)         // 55296 B

__global__ __launch_bounds__(256) void gemm_tf32(
    const float* __restrict__ A, const float* __restrict__ B,
    const float* __restrict__ bias, float* __restrict__ C,
    int M, int N, int K, float outscale, int conv_out)
{
    extern __shared__ unsigned gsm[];
    const uint32_t sbase = (uint32_t)__cvta_generic_to_shared(gsm);

    const int tid  = threadIdx.x;
    const int lane = tid & 31;
    const int w    = tid >> 5;
    const int g    = lane >> 2;
    const int t    = lane & 3;
    const int wm   = (w & 3) * 32;
    const int wn   = (w >> 2) * 32;
    const int row0 = blockIdx.y * TBM;
    const int col0 = blockIdx.x * TBN;

    float c[2][4][4];
#pragma unroll
    for (int mi = 0; mi < 2; mi++)
#pragma unroll
        for (int ni = 0; ni < 4; ni++)
#pragma unroll
            for (int r = 0; r < 4; r++) c[mi][ni][r] = 0.0f;

    const int nk = K / TBK;

    // stage loader
    auto load_tile = [&](int k0, int buf) {
#pragma unroll
        for (int i = 0; i < 4; i++) {
            int id = tid + 256 * i, r = id >> 3, cc = id & 7;
            cp16(sbase + (uint32_t)(buf * GBUF + r * ASTR + cc * 4) * 4,
                 A + (size_t)(row0 + r) * K + k0 + cc * 4);
        }
#pragma unroll
        for (int i = 0; i < 2; i++) {
            int id = tid + 256 * i, r = id >> 4, cc = id & 15;
            cp16(sbase + (uint32_t)(buf * GBUF + TBM * ASTR + r * BSTR + cc * 4) * 4,
                 B + (size_t)(k0 + r) * N + col0 + cc * 4);
        }
    };

    load_tile(0, 0);
    CP_COMMIT();

    for (int kt = 0; kt < nk; kt++) {
        CP_WAIT0();
        __syncthreads();
        if (kt + 1 < nk) {
            load_tile((kt + 1) * TBK, (kt + 1) & 1);
            CP_COMMIT();
        }
        const unsigned* Asb = gsm + (kt & 1) * GBUF;
        const unsigned* Bsb = Asb + TBM * ASTR;
#pragma unroll
        for (int kp = 0; kp < 4; kp++) {
            unsigned af[2][4], bf[4][2];
#pragma unroll
            for (int mi = 0; mi < 2; mi++) {
                int r0 = (wm + mi * 16 + g) * ASTR + kp * 8 + t;
                int r1 = (wm + mi * 16 + g + 8) * ASTR + kp * 8 + t;
                af[mi][0] = Asb[r0];
                af[mi][1] = Asb[r1];
                af[mi][2] = Asb[r0 + 4];
                af[mi][3] = Asb[r1 + 4];
            }
#pragma unroll
            for (int ni = 0; ni < 4; ni++) {
                bf[ni][0] = Bsb[(kp * 8 + t) * BSTR + wn + ni * 8 + g];
                bf[ni][1] = Bsb[(kp * 8 + t + 4) * BSTR + wn + ni * 8 + g];
            }
#pragma unroll
            for (int mi = 0; mi < 2; mi++)
#pragma unroll
                for (int ni = 0; ni < 4; ni++)
                    mma8(c[mi][ni], af[mi], bf[ni]);
        }
        __syncthreads();
    }

    // epilogue
#pragma unroll
    for (int ni = 0; ni < 4; ni++) {
        int col = col0 + wn + ni * 8 + 2 * t;
        float2 bv = make_float2(0.0f, 0.0f);
        if (bias) bv = *(const float2*)(bias + col);
#pragma unroll
        for (int mi = 0; mi < 2; mi++) {
            int r0 = row0 + wm + mi * 16 + g;
            float o00 = c[mi][ni][0] * outscale + bv.x;
            float o01 = c[mi][ni][1] * outscale + bv.y;
            float o10 = c[mi][ni][2] * outscale + bv.x;
            float o11 = c[mi][ni][3] * outscale + bv.y;
            if (conv_out) {
                o00 = __uint_as_float(f2tf(o00));
                o01 = __uint_as_float(f2tf(o01));
                o10 = __uint_as_float(f2tf(o10));
                o11 = __uint_as_float(f2tf(o11));
            }
            *(float2*)(C + (size_t)r0 * N + col) = make_float2(o00, o01);
            *(float2*)(C + (size_t)(r0 + 8) * N + col) = make_float2(o10, o11);
        }
    }
}

// ---------------------------------------------------------------------------
// Flash attention. Block = (b, h, 128-row Q tile), 128 thr, warp = 32 Q rows.
// Q resident in smem; K/V cp.async double-buffered; P via register shuffles
// (no smem round-trip, no extra block sync). Inputs are tf32 bit patterns,
// Q pre-scaled by 0.125*log2(e) in its GEMM epilogue.
// ---------------------------------------------------------------------------
#define QSTR 68
#define KSTR 68
#define VSTR 72
#define QWORDS (128 * QSTR)          // 8704
#define KWORDS (64 * KSTR)           // 4352
#define VWORDS (64 * VSTR)           // 4608
#define KOFF   QWORDS
#define VOFF   (QWORDS + 2 * KWORDS)
#define ATTN_SMEM ((QWORDS + 2 * KWORDS + 2 * VWORDS) * 4)   // 106496 B

__global__ __launch_bounds__(128) void attn_tf32(
    const float* __restrict__ Q, const float* __restrict__ K,
    const float* __restrict__ V, float* __restrict__ O)
{
    extern __shared__ unsigned smem[];
    const uint32_t sbase = (uint32_t)__cvta_generic_to_shared(smem);

    const int tid  = threadIdx.x;
    const int lane = tid & 31;
    const int w    = tid >> 5;
    const int g    = lane >> 2;
    const int t    = lane & 3;
    const int qt   = (gridDim.x - 1) - blockIdx.x;   // big tiles first
    const int h    = blockIdx.y;
    const int b    = blockIdx.z;

    const float* Qptr = Q + ((size_t)(b * SEQ + qt * 128)) * DMODEL + h * HDIM;

    // prologue: Q tile + stage 0 K/V, one cp.async group
#pragma unroll
    for (int i = 0; i < 16; i++) {
        int id = tid + 128 * i, r = id >> 4, cc = id & 15;
        cp16(sbase + (uint32_t)(r * QSTR + cc * 4) * 4, Qptr + (size_t)r * DMODEL + cc * 4);
    }
    auto load_kv = [&](int kt, int buf) {
        const size_t kvb = ((size_t)(b * SEQ + kt * 64)) * DMODEL + h * HDIM;
#pragma unroll
        for (int i = 0; i < 8; i++) {
            int id = tid + 128 * i, r = id >> 4, cc = id & 15;
            cp16(sbase + (uint32_t)(KOFF + buf * KWORDS + r * KSTR + cc * 4) * 4,
                 K + kvb + (size_t)r * DMODEL + cc * 4);
            cp16(sbase + (uint32_t)(VOFF + buf * VWORDS + r * VSTR + cc * 4) * 4,
                 V + kvb + (size_t)r * DMODEL + cc * 4);
        }
    };
    load_kv(0, 0);
    CP_COMMIT();

    float co[2][8][4];
#pragma unroll
    for (int mi = 0; mi < 2; mi++)
#pragma unroll
        for (int ni = 0; ni < 8; ni++)
#pragma unroll
            for (int r = 0; r < 4; r++) co[mi][ni][r] = 0.0f;
    float mA[2] = {-1e30f, -1e30f}, mB[2] = {-1e30f, -1e30f};
    float lA[2] = {0.0f, 0.0f},     lB[2] = {0.0f, 0.0f};

    const int ntiles = 2 * qt + 2;
    const int srcA = (lane & ~3) | (t >> 1);
    const int srcB = srcA + 2;
    const bool hi = (t & 1);

    for (int kt = 0; kt < ntiles; kt++) {
        CP_WAIT0();
        __syncthreads();
        if (kt + 1 < ntiles) {
            load_kv(kt + 1, (kt + 1) & 1);
            CP_COMMIT();
        }
        const unsigned* Kb = smem + KOFF + (kt & 1) * KWORDS;
        const unsigned* Vb = smem + VOFF + (kt & 1) * VWORDS;

        // ---- S = Q K^T ----
        float cs[2][8][4];
#pragma unroll
        for (int mi = 0; mi < 2; mi++)
#pragma unroll
            for (int ni = 0; ni < 8; ni++)
#pragma unroll
                for (int r = 0; r < 4; r++) cs[mi][ni][r] = 0.0f;
#pragma unroll
        for (int kp = 0; kp < 8; kp++) {
            unsigned af[2][4];
#pragma unroll
            for (int mi = 0; mi < 2; mi++) {
                int r0 = (w * 32 + mi * 16 + g) * QSTR + kp * 8 + t;
                int r1 = r0 + 8 * QSTR;
                af[mi][0] = smem[r0];
                af[mi][1] = smem[r1];
                af[mi][2] = smem[r0 + 4];
                af[mi][3] = smem[r1 + 4];
            }
#pragma unroll
            for (int ni = 0; ni < 8; ni++) {
                unsigned bf[2];
                int rr = (ni * 8 + g) * KSTR + kp * 8 + t;
                bf[0] = Kb[rr];
                bf[1] = Kb[rr + 4];
                mma8(cs[0][ni], af[0], bf);
                mma8(cs[1][ni], af[1], bf);
            }
        }

        // ---- causal mask (last two tiles only) ----
        if (kt >= 2 * qt) {
            const int cb = kt * 64 + 2 * t;
            const int rb = qt * 128 + w * 32 + g;
#pragma unroll
            for (int mi = 0; mi < 2; mi++) {
                int r0 = rb + mi * 16;
#pragma unroll
                for (int ni = 0; ni < 8; ni++) {
                    int col = cb + ni * 8;
                    if (col > r0)         cs[mi][ni][0] = -1e30f;
                    if (col + 1 > r0)     cs[mi][ni][1] = -1e30f;
                    if (col > r0 + 8)     cs[mi][ni][2] = -1e30f;
                    if (col + 1 > r0 + 8) cs[mi][ni][3] = -1e30f;
                }
            }
        }

        // ---- online softmax (base-2) ----
#pragma unroll
        for (int mi = 0; mi < 2; mi++) {
            float tm0 = -1e30f, tm1 = -1e30f;
#pragma unroll
            for (int ni = 0; ni < 8; ni++) {
                tm0 = fmaxf(tm0, fmaxf(cs[mi][ni][0], cs[mi][ni][1]));
                tm1 = fmaxf(tm1, fmaxf(cs[mi][ni][2], cs[mi][ni][3]));
            }
            tm0 = fmaxf(tm0, __shfl_xor_sync(0xffffffffu, tm0, 1));
            tm0 = fmaxf(tm0, __shfl_xor_sync(0xffffffffu, tm0, 2));
            tm1 = fmaxf(tm1, __shfl_xor_sync(0xffffffffu, tm1, 1));
            tm1 = fmaxf(tm1, __shfl_xor_sync(0xffffffffu, tm1, 2));

            float mn0 = fmaxf(mA[mi], tm0), mn1 = fmaxf(mB[mi], tm1);
            float al0 = ex2f(mA[mi] - mn0), al1 = ex2f(mB[mi] - mn1);
            float s0 = 0.0f, s1 = 0.0f;
#pragma unroll
            for (int ni = 0; ni < 8; ni++) {
                float p0 = ex2f(cs[mi][ni][0] - mn0); s0 += p0;
                float p1 = ex2f(cs[mi][ni][1] - mn0); s0 += p1;
                float p2 = ex2f(cs[mi][ni][2] - mn1); s1 += p2;
                float p3 = ex2f(cs[mi][ni][3] - mn1); s1 += p3;
                cs[mi][ni][0] = __uint_as_float(f2tf(p0));
                cs[mi][ni][1] = __uint_as_float(f2tf(p1));
                cs[mi][ni][2] = __uint_as_float(f2tf(p2));
                cs[mi][ni][3] = __uint_as_float(f2tf(p3));
            }
            s0 += __shfl_xor_sync(0xffffffffu, s0, 1);
            s0 += __shfl_xor_sync(0xffffffffu, s0, 2);
            s1 += __shfl_xor_sync(0xffffffffu, s1, 1);
            s1 += __shfl_xor_sync(0xffffffffu, s1, 2);
            lA[mi] = lA[mi] * al0 + s0;
            lB[mi] = lB[mi] * al1 + s1;
            mA[mi] = mn0; mB[mi] = mn1;
#pragma unroll
            for (int ni = 0; ni < 8; ni++) {
                co[mi][ni][0] *= al0; co[mi][ni][1] *= al0;
                co[mi][ni][2] *= al1; co[mi][ni][3] *= al1;
            }
        }

        // ---- O += P V : P C-frags -> A-frags via quad shuffles ----
#pragma unroll
        for (int kp = 0; kp < 8; kp++) {
            unsigned ap[2][4];
#pragma unroll
            for (int mi = 0; mi < 2; mi++) {
                float x0 = __shfl_sync(0xffffffffu, cs[mi][kp][0], srcA);
                float x1 = __shfl_sync(0xffffffffu, cs[mi][kp][1], srcA);
                float y0 = __shfl_sync(0xffffffffu, cs[mi][kp][2], srcA);
                float y1 = __shfl_sync(0xffffffffu, cs[mi][kp][3], srcA);
                float z0 = __shfl_sync(0xffffffffu, cs[mi][kp][0], srcB);
                float z1 = __shfl_sync(0xffffffffu, cs[mi][kp][1], srcB);
                float u0 = __shfl_sync(0xffffffffu, cs[mi][kp][2], srcB);
                float u1 = __shfl_sync(0xffffffffu, cs[mi][kp][3], srcB);
                ap[mi][0] = __float_as_uint(hi ? x1 : x0);
                ap[mi][1] = __float_as_uint(hi ? y1 : y0);
                ap[mi][2] = __float_as_uint(hi ? z1 : z0);
                ap[mi][3] = __float_as_uint(hi ? u1 : u0);
            }
#pragma unroll
            for (int ni = 0; ni < 8; ni++) {
                unsigned bf[2];
                bf[0] = Vb[(kp * 8 + t) * VSTR + ni * 8 + g];
                bf[1] = Vb[(kp * 8 + t + 4) * VSTR + ni * 8 + g];
                mma8(co[0][ni], ap[0], bf);
                mma8(co[1][ni], ap[1], bf);
            }
        }
    }

    // epilogue: write tf32-rounded ctx (feeds tf32 out-proj GEMM)
#pragma unroll
    for (int mi = 0; mi < 2; mi++) {
        const float i0 = 1.0f / lA[mi], i1 = 1.0f / lB[mi];
        size_t rbase = ((size_t)(b * SEQ + qt * 128 + w * 32 + mi * 16 + g)) * DMODEL + h * HDIM;
#pragma unroll
        for (int ni = 0; ni < 8; ni++) {
            size_t r0 = rbase + ni * 8 + 2 * t;
            *(float2*)(O + r0) = make_float2(
                __uint_as_float(f2tf(co[mi][ni][0] * i0)),
                __uint_as_float(f2tf(co[mi][ni][1] * i0)));
            *(float2*)(O + r0 + (size_t)8 * DMODEL) = make_float2(
                __uint_as_float(f2tf(co[mi][ni][2] * i1)),
                __uint_as_float(f2tf(co[mi][ni][3] * i1)));
        }
    }
}

// ---------------------------------------------------------------------------
extern "C" void kernel_launch(void* const* d_in, const int* in_sizes, int n_in,
                              void* d_out, int out_size)
{
    (void)in_sizes; (void)n_in; (void)out_size;
    const float* x  = (const float*)d_in[0];
    const float* wq = (const float*)d_in[1];
    const float* wk = (const float*)d_in[2];
    const float* wv = (const float*)d_in[3];
    const float* wo = (const float*)d_in[4];
    const float* bo = (const float*)d_in[5];
    float* out = (float*)d_out;

    float *xt, *wt, *qp, *kp, *vp, *cp;
    cudaGetSymbolAddress((void**)&xt, g_xt);
    cudaGetSymbolAddress((void**)&wt, g_wt);
    cudaGetSymbolAddress((void**)&qp, g_q);
    cudaGetSymbolAddress((void**)&kp, g_k);
    cudaGetSymbolAddress((void**)&vp, g_v);
    cudaGetSymbolAddress((void**)&cp, g_ctx);

    static bool attr_done = false;
    if (!attr_done) {
        cudaFuncSetAttribute(gemm_tf32, cudaFuncAttributeMaxDynamicSharedMemorySize, GEMM_SMEM);
        cudaFuncSetAttribute(attn_tf32, cudaFuncAttributeMaxDynamicSharedMemorySize, ATTN_SMEM);
        attr_done = true;
    }

    // prep: tf32-round x and weights
    const int NX4 = MTOT * DMODEL / 4;       // 1572864
    const int NW4 = DMODEL * DMODEL / 4;     // 147456
    prep_tf32<<<(NX4 + 255) / 256, 256>>>(x, xt, NX4);
    prep_tf32<<<(NW4 + 255) / 256, 256>>>(wq, wt + 0 * DMODEL * DMODEL, NW4);
    prep_tf32<<<(NW4 + 255) / 256, 256>>>(wk, wt + 1 * DMODEL * DMODEL, NW4);
    prep_tf32<<<(NW4 + 255) / 256, 256>>>(wv, wt + 2 * DMODEL * DMODEL, NW4);
    prep_tf32<<<(NW4 + 255) / 256, 256>>>(wo, wt + 3 * DMODEL * DMODEL, NW4);

    const float qscale = 0.125f * 1.4426950408889634f;  // 1/sqrt(64) * log2(e)
    dim3 gemm_grid(DMODEL / TBN, MTOT / TBM);   // (12, 64)
    gemm_tf32<<<gemm_grid, 256, GEMM_SMEM>>>(xt, wt + 0 * DMODEL * DMODEL, nullptr, qp,
                                             MTOT, DMODEL, DMODEL, qscale, 1);
    gemm_tf32<<<gemm_grid, 256, GEMM_SMEM>>>(xt, wt + 1 * DMODEL * DMODEL, nullptr, kp,
                                             MTOT, DMODEL, DMODEL, 1.0f, 1);
    gemm_tf32<<<gemm_grid, 256, GEMM_SMEM>>>(xt, wt + 2 * DMODEL * DMODEL, nullptr, vp,
                                             MTOT, DMODEL, DMODEL, 1.0f, 1);

    dim3 attn_grid(SEQ / 128, NHEADS, BB);      // (32, 12, 2)
    attn_tf32<<<attn_grid, 128, ATTN_SMEM>>>(qp, kp, vp, cp);

    gemm_tf32<<<gemm_grid, 256, GEMM_SMEM>>>(cp, wt + 3 * DMODEL * DMODEL, bo, out,
                                             MTOT, DMODEL, DMODEL, 1.0f, 0);
}

// round 6
// speedup vs baseline: 4.9619x; 1.0991x over previous
#include <cuda_runtime.h>
#include <cstddef>
#include <cstdint>

#define BB 2
#define SEQ 4096
#define DMODEL 768
#define NHEADS 12
#define HDIM 64
#define MTOT (BB * SEQ)   // 8192

// Scratch (alloc-free rule: __device__ globals)
__device__ float g_xt[MTOT * DMODEL];            // x, tf32-rounded
__device__ float g_wt[4 * DMODEL * DMODEL];      // wq,wk,wv,wo tf32-rounded
__device__ float g_q[MTOT * DMODEL];
__device__ float g_k[MTOT * DMODEL];
__device__ float g_v[MTOT * DMODEL];
__device__ float g_ctx[MTOT * DMODEL];

// ---------------------------------------------------------------------------
// helpers
// ---------------------------------------------------------------------------
__device__ __forceinline__ unsigned f2tf(float f) {
    unsigned u;
    asm("cvt.rna.tf32.f32 %0, %1;" : "=r"(u) : "f"(f));
    return u;
}
__device__ __forceinline__ float ex2f(float x) {
    float y;
    asm("ex2.approx.f32 %0, %1;" : "=f"(y) : "f"(x));
    return y;
}
__device__ __forceinline__ void mma8(float c[4], const unsigned a[4], const unsigned b[2]) {
    asm volatile(
        "mma.sync.aligned.m16n8k8.row.col.f32.tf32.tf32.f32 "
        "{%0,%1,%2,%3}, {%4,%5,%6,%7}, {%8,%9}, {%0,%1,%2,%3};\n"
        : "+f"(c[0]), "+f"(c[1]), "+f"(c[2]), "+f"(c[3])
        : "r"(a[0]), "r"(a[1]), "r"(a[2]), "r"(a[3]), "r"(b[0]), "r"(b[1]));
}
__device__ __forceinline__ void cp16(uint32_t dst, const void* src) {
    asm volatile("cp.async.cg.shared.global [%0], [%1], 16;\n" :: "r"(dst), "l"(src));
}
#define CP_COMMIT() asm volatile("cp.async.commit_group;\n" ::: "memory")
#define CP_WAIT0()  asm volatile("cp.async.wait_group 0;\n" ::: "memory")

// ---------------------------------------------------------------------------
// prep: fp32 -> tf32-rounded fp32 (elementwise, float4)
// ---------------------------------------------------------------------------
__global__ void prep_tf32(const float* __restrict__ src, float* __restrict__ dst, int n4)
{
    int i = blockIdx.x * blockDim.x + threadIdx.x;
    if (i >= n4) return;
    float4 v = ((const float4*)src)[i];
    v.x = __uint_as_float(f2tf(v.x));
    v.y = __uint_as_float(f2tf(v.y));
    v.z = __uint_as_float(f2tf(v.z));
    v.w = __uint_as_float(f2tf(v.w));
    ((float4*)dst)[i] = v;
}

// 4 weight matrices in one launch (blockIdx.y selects matrix)
__global__ void prep_tf32_w(const float* __restrict__ w0, const float* __restrict__ w1,
                            const float* __restrict__ w2, const float* __restrict__ w3,
                            float* __restrict__ dst, int n4)
{
    int i = blockIdx.x * blockDim.x + threadIdx.x;
    if (i >= n4) return;
    const float* src = (blockIdx.y == 0) ? w0 : (blockIdx.y == 1) ? w1
                     : (blockIdx.y == 2) ? w2 : w3;
    float4 v = ((const float4*)src)[i];
    v.x = __uint_as_float(f2tf(v.x));
    v.y = __uint_as_float(f2tf(v.y));
    v.z = __uint_as_float(f2tf(v.z));
    v.w = __uint_as_float(f2tf(v.w));
    ((float4*)(dst + (size_t)blockIdx.y * DMODEL * DMODEL))[i] = v;
}

// ---------------------------------------------------------------------------
// tf32 GEMM: C = A@B (*outscale, +bias, optional tf32-round of output).
// Inputs already tf32 bit patterns. 256 thr, tile 128x64x32, cp.async 2-stage.
// ---------------------------------------------------------------------------
#define TBM 128
#define TBN 64
#define TBK 32
#define ASTR 36
#define BSTR 72
#define GBUF (TBM * ASTR + TBK * BSTR)   // 6912 words per stage
#define GEMM_SMEM (2 * GBUF * 4)         // 55296 B

__global__ __launch_bounds__(256) void gemm_tf32(
    const float* __restrict__ A, const float* __restrict__ B,
    const float* __restrict__ bias, float* __restrict__ C,
    int M, int N, int K, float outscale, int conv_out)
{
    extern __shared__ unsigned gsm[];
    const uint32_t sbase = (uint32_t)__cvta_generic_to_shared(gsm);

    const int tid  = threadIdx.x;
    const int lane = tid & 31;
    const int w    = tid >> 5;
    const int g    = lane >> 2;
    const int t    = lane & 3;
    const int wm   = (w & 3) * 32;
    const int wn   = (w >> 2) * 32;
    const int row0 = blockIdx.y * TBM;
    const int col0 = blockIdx.x * TBN;

    float c[2][4][4];
#pragma unroll
    for (int mi = 0; mi < 2; mi++)
#pragma unroll
        for (int ni = 0; ni < 4; ni++)
#pragma unroll
            for (int r = 0; r < 4; r++) c[mi][ni][r] = 0.0f;

    const int nk = K / TBK;

    auto load_tile = [&](int k0, int buf) {
#pragma unroll
        for (int i = 0; i < 4; i++) {
            int id = tid + 256 * i, r = id >> 3, cc = id & 7;
            cp16(sbase + (uint32_t)(buf * GBUF + r * ASTR + cc * 4) * 4,
                 A + (size_t)(row0 + r) * K + k0 + cc * 4);
        }
#pragma unroll
        for (int i = 0; i < 2; i++) {
            int id = tid + 256 * i, r = id >> 4, cc = id & 15;
            cp16(sbase + (uint32_t)(buf * GBUF + TBM * ASTR + r * BSTR + cc * 4) * 4,
                 B + (size_t)(k0 + r) * N + col0 + cc * 4);
        }
    };

    load_tile(0, 0);
    CP_COMMIT();

    for (int kt = 0; kt < nk; kt++) {
        CP_WAIT0();
        __syncthreads();
        if (kt + 1 < nk) {
            load_tile((kt + 1) * TBK, (kt + 1) & 1);
            CP_COMMIT();
        }
        const unsigned* Asb = gsm + (kt & 1) * GBUF;
        const unsigned* Bsb = Asb + TBM * ASTR;
#pragma unroll
        for (int kp = 0; kp < 4; kp++) {
            unsigned af[2][4], bf[4][2];
#pragma unroll
            for (int mi = 0; mi < 2; mi++) {
                int r0 = (wm + mi * 16 + g) * ASTR + kp * 8 + t;
                int r1 = (wm + mi * 16 + g + 8) * ASTR + kp * 8 + t;
                af[mi][0] = Asb[r0];
                af[mi][1] = Asb[r1];
                af[mi][2] = Asb[r0 + 4];
                af[mi][3] = Asb[r1 + 4];
            }
#pragma unroll
            for (int ni = 0; ni < 4; ni++) {
                bf[ni][0] = Bsb[(kp * 8 + t) * BSTR + wn + ni * 8 + g];
                bf[ni][1] = Bsb[(kp * 8 + t + 4) * BSTR + wn + ni * 8 + g];
            }
#pragma unroll
            for (int mi = 0; mi < 2; mi++)
#pragma unroll
                for (int ni = 0; ni < 4; ni++)
                    mma8(c[mi][ni], af[mi], bf[ni]);
        }
        __syncthreads();
    }

#pragma unroll
    for (int ni = 0; ni < 4; ni++) {
        int col = col0 + wn + ni * 8 + 2 * t;
        float2 bv = make_float2(0.0f, 0.0f);
        if (bias) bv = *(const float2*)(bias + col);
#pragma unroll
        for (int mi = 0; mi < 2; mi++) {
            int r0 = row0 + wm + mi * 16 + g;
            float o00 = c[mi][ni][0] * outscale + bv.x;
            float o01 = c[mi][ni][1] * outscale + bv.y;
            float o10 = c[mi][ni][2] * outscale + bv.x;
            float o11 = c[mi][ni][3] * outscale + bv.y;
            if (conv_out) {
                o00 = __uint_as_float(f2tf(o00));
                o01 = __uint_as_float(f2tf(o01));
                o10 = __uint_as_float(f2tf(o10));
                o11 = __uint_as_float(f2tf(o11));
            }
            *(float2*)(C + (size_t)r0 * N + col) = make_float2(o00, o01);
            *(float2*)(C + (size_t)(r0 + 8) * N + col) = make_float2(o10, o11);
        }
    }
}

// ---------------------------------------------------------------------------
// Flash attention. Block = (b, h, 128-row Q tile), 128 thr, warp = 32 Q rows.
// Q fragments in REGISTERS (staged once through smem); smem = 2 K/V stages
// only (70KB) -> 2 CTAs/SM. P via register shuffles. tf32 inputs, Q
// pre-scaled by 0.125*log2(e).
// ---------------------------------------------------------------------------
#define QSTR 68
#define KSTR 68
#define VSTR 72
#define KWORDS (64 * KSTR)             // 4352
#define VWORDS (64 * VSTR)             // 4608
#define STG    (KWORDS + VWORDS)       // 8960 words per stage
#define ATTN_SMEM (2 * STG * 4)        // 71680 B

__global__ __launch_bounds__(128, 2) void attn_tf32(
    const float* __restrict__ Q, const float* __restrict__ K,
    const float* __restrict__ V, float* __restrict__ O)
{
    extern __shared__ unsigned smem[];
    const uint32_t sbase = (uint32_t)__cvta_generic_to_shared(smem);

    const int tid  = threadIdx.x;
    const int lane = tid & 31;
    const int w    = tid >> 5;
    const int g    = lane >> 2;
    const int t    = lane & 3;
    const int qt   = (gridDim.x - 1) - blockIdx.x;   // big tiles first
    const int h    = blockIdx.y;
    const int b    = blockIdx.z;

    const float* Qptr = Q + ((size_t)(b * SEQ + qt * 128)) * DMODEL + h * HDIM;

    // stage Q tile through smem (uses stage-0/1 region), extract to regs
#pragma unroll
    for (int i = 0; i < 16; i++) {
        int id = tid + 128 * i, r = id >> 4, cc = id & 15;
        cp16(sbase + (uint32_t)(r * QSTR + cc * 4) * 4, Qptr + (size_t)r * DMODEL + cc * 4);
    }
    CP_COMMIT();
    CP_WAIT0();
    __syncthreads();

    unsigned aq[8][2][4];   // [kp][mi][frag]
#pragma unroll
    for (int kp = 0; kp < 8; kp++)
#pragma unroll
        for (int mi = 0; mi < 2; mi++) {
            int r0 = (w * 32 + mi * 16 + g) * QSTR + kp * 8 + t;
            int r1 = r0 + 8 * QSTR;
            aq[kp][mi][0] = smem[r0];
            aq[kp][mi][1] = smem[r1];
            aq[kp][mi][2] = smem[r0 + 4];
            aq[kp][mi][3] = smem[r1 + 4];
        }
    __syncthreads();   // everyone extracted before K/V overwrites

    auto load_kv = [&](int kt, int buf) {
        const size_t kvb = ((size_t)(b * SEQ + kt * 64)) * DMODEL + h * HDIM;
#pragma unroll
        for (int i = 0; i < 8; i++) {
            int id = tid + 128 * i, r = id >> 4, cc = id & 15;
            cp16(sbase + (uint32_t)(buf * STG + r * KSTR + cc * 4) * 4,
                 K + kvb + (size_t)r * DMODEL + cc * 4);
            cp16(sbase + (uint32_t)(buf * STG + KWORDS + r * VSTR + cc * 4) * 4,
                 V + kvb + (size_t)r * DMODEL + cc * 4);
        }
    };
    load_kv(0, 0);
    CP_COMMIT();

    float co[2][8][4];
#pragma unroll
    for (int mi = 0; mi < 2; mi++)
#pragma unroll
        for (int ni = 0; ni < 8; ni++)
#pragma unroll
            for (int r = 0; r < 4; r++) co[mi][ni][r] = 0.0f;
    float mA[2] = {-1e30f, -1e30f}, mB[2] = {-1e30f, -1e30f};
    float lA[2] = {0.0f, 0.0f},     lB[2] = {0.0f, 0.0f};

    const int ntiles = 2 * qt + 2;
    const int srcA = (lane & ~3) | (t >> 1);
    const int srcB = srcA + 2;
    const bool hi = (t & 1);

    for (int kt = 0; kt < ntiles; kt++) {
        CP_WAIT0();
        __syncthreads();
        if (kt + 1 < ntiles) {
            load_kv(kt + 1, (kt + 1) & 1);
            CP_COMMIT();
        }
        const unsigned* Kb = smem + (kt & 1) * STG;
        const unsigned* Vb = Kb + KWORDS;

        // ---- S = Q K^T ----
        float cs[2][8][4];
#pragma unroll
        for (int mi = 0; mi < 2; mi++)
#pragma unroll
            for (int ni = 0; ni < 8; ni++)
#pragma unroll
                for (int r = 0; r < 4; r++) cs[mi][ni][r] = 0.0f;
#pragma unroll
        for (int kp = 0; kp < 8; kp++) {
#pragma unroll
            for (int ni = 0; ni < 8; ni++) {
                unsigned bf[2];
                int rr = (ni * 8 + g) * KSTR + kp * 8 + t;
                bf[0] = Kb[rr];
                bf[1] = Kb[rr + 4];
                mma8(cs[0][ni], aq[kp][0], bf);
                mma8(cs[1][ni], aq[kp][1], bf);
            }
        }

        // ---- causal mask (last two tiles only) ----
        if (kt >= 2 * qt) {
            const int cb = kt * 64 + 2 * t;
            const int rb = qt * 128 + w * 32 + g;
#pragma unroll
            for (int mi = 0; mi < 2; mi++) {
                int r0 = rb + mi * 16;
#pragma unroll
                for (int ni = 0; ni < 8; ni++) {
                    int col = cb + ni * 8;
                    if (col > r0)         cs[mi][ni][0] = -1e30f;
                    if (col + 1 > r0)     cs[mi][ni][1] = -1e30f;
                    if (col > r0 + 8)     cs[mi][ni][2] = -1e30f;
                    if (col + 1 > r0 + 8) cs[mi][ni][3] = -1e30f;
                }
            }
        }

        // ---- online softmax (base-2) ----
#pragma unroll
        for (int mi = 0; mi < 2; mi++) {
            float tm0 = -1e30f, tm1 = -1e30f;
#pragma unroll
            for (int ni = 0; ni < 8; ni++) {
                tm0 = fmaxf(tm0, fmaxf(cs[mi][ni][0], cs[mi][ni][1]));
                tm1 = fmaxf(tm1, fmaxf(cs[mi][ni][2], cs[mi][ni][3]));
            }
            tm0 = fmaxf(tm0, __shfl_xor_sync(0xffffffffu, tm0, 1));
            tm0 = fmaxf(tm0, __shfl_xor_sync(0xffffffffu, tm0, 2));
            tm1 = fmaxf(tm1, __shfl_xor_sync(0xffffffffu, tm1, 1));
            tm1 = fmaxf(tm1, __shfl_xor_sync(0xffffffffu, tm1, 2));

            float mn0 = fmaxf(mA[mi], tm0), mn1 = fmaxf(mB[mi], tm1);
            float al0 = ex2f(mA[mi] - mn0), al1 = ex2f(mB[mi] - mn1);
            float s0 = 0.0f, s1 = 0.0f;
#pragma unroll
            for (int ni = 0; ni < 8; ni++) {
                float p0 = ex2f(cs[mi][ni][0] - mn0); s0 += p0;
                float p1 = ex2f(cs[mi][ni][1] - mn0); s0 += p1;
                float p2 = ex2f(cs[mi][ni][2] - mn1); s1 += p2;
                float p3 = ex2f(cs[mi][ni][3] - mn1); s1 += p3;
                cs[mi][ni][0] = __uint_as_float(f2tf(p0));
                cs[mi][ni][1] = __uint_as_float(f2tf(p1));
                cs[mi][ni][2] = __uint_as_float(f2tf(p2));
                cs[mi][ni][3] = __uint_as_float(f2tf(p3));
            }
            s0 += __shfl_xor_sync(0xffffffffu, s0, 1);
            s0 += __shfl_xor_sync(0xffffffffu, s0, 2);
            s1 += __shfl_xor_sync(0xffffffffu, s1, 1);
            s1 += __shfl_xor_sync(0xffffffffu, s1, 2);
            lA[mi] = lA[mi] * al0 + s0;
            lB[mi] = lB[mi] * al1 + s1;
            mA[mi] = mn0; mB[mi] = mn1;
#pragma unroll
            for (int ni = 0; ni < 8; ni++) {
                co[mi][ni][0] *= al0; co[mi][ni][1] *= al0;
                co[mi][ni][2] *= al1; co[mi][ni][3] *= al1;
            }
        }

        // ---- O += P V : P C-frags -> A-frags via quad shuffles ----
#pragma unroll
        for (int kp = 0; kp < 8; kp++) {
            unsigned ap[2][4];
#pragma unroll
            for (int mi = 0; mi < 2; mi++) {
                float x0 = __shfl_sync(0xffffffffu, cs[mi][kp][0], srcA);
                float x1 = __shfl_sync(0xffffffffu, cs[mi][kp][1], srcA);
                float y0 = __shfl_sync(0xffffffffu, cs[mi][kp][2], srcA);
                float y1 = __shfl_sync(0xffffffffu, cs[mi][kp][3], srcA);
                float z0 = __shfl_sync(0xffffffffu, cs[mi][kp][0], srcB);
                float z1 = __shfl_sync(0xffffffffu, cs[mi][kp][1], srcB);
                float u0 = __shfl_sync(0xffffffffu, cs[mi][kp][2], srcB);
                float u1 = __shfl_sync(0xffffffffu, cs[mi][kp][3], srcB);
                ap[mi][0] = __float_as_uint(hi ? x1 : x0);
                ap[mi][1] = __float_as_uint(hi ? y1 : y0);
                ap[mi][2] = __float_as_uint(hi ? z1 : z0);
                ap[mi][3] = __float_as_uint(hi ? u1 : u0);
            }
#pragma unroll
            for (int ni = 0; ni < 8; ni++) {
                unsigned bf[2];
                bf[0] = Vb[(kp * 8 + t) * VSTR + ni * 8 + g];
                bf[1] = Vb[(kp * 8 + t + 4) * VSTR + ni * 8 + g];
                mma8(co[0][ni], ap[0], bf);
                mma8(co[1][ni], ap[1], bf);
            }
        }
    }

    // epilogue: write tf32-rounded ctx (feeds tf32 out-proj GEMM)
#pragma unroll
    for (int mi = 0; mi < 2; mi++) {
        const float i0 = 1.0f / lA[mi], i1 = 1.0f / lB[mi];
        size_t rbase = ((size_t)(b * SEQ + qt * 128 + w * 32 + mi * 16 + g)) * DMODEL + h * HDIM;
#pragma unroll
        for (int ni = 0; ni < 8; ni++) {
            size_t r0 = rbase + ni * 8 + 2 * t;
            *(float2*)(O + r0) = make_float2(
                __uint_as_float(f2tf(co[mi][ni][0] * i0)),
                __uint_as_float(f2tf(co[mi][ni][1] * i0)));
            *(float2*)(O + r0 + (size_t)8 * DMODEL) = make_float2(
                __uint_as_float(f2tf(co[mi][ni][2] * i1)),
                __uint_as_float(f2tf(co[mi][ni][3] * i1)));
        }
    }
}

// ---------------------------------------------------------------------------
extern "C" void kernel_launch(void* const* d_in, const int* in_sizes, int n_in,
                              void* d_out, int out_size)
{
    (void)in_sizes; (void)n_in; (void)out_size;
    const float* x  = (const float*)d_in[0];
    const float* wq = (const float*)d_in[1];
    const float* wk = (const float*)d_in[2];
    const float* wv = (const float*)d_in[3];
    const float* wo = (const float*)d_in[4];
    const float* bo = (const float*)d_in[5];
    float* out = (float*)d_out;

    float *xt, *wt, *qp, *kp, *vp, *cp;
    cudaGetSymbolAddress((void**)&xt, g_xt);
    cudaGetSymbolAddress((void**)&wt, g_wt);
    cudaGetSymbolAddress((void**)&qp, g_q);
    cudaGetSymbolAddress((void**)&kp, g_k);
    cudaGetSymbolAddress((void**)&vp, g_v);
    cudaGetSymbolAddress((void**)&cp, g_ctx);

    static bool attr_done = false;
    if (!attr_done) {
        cudaFuncSetAttribute(gemm_tf32, cudaFuncAttributeMaxDynamicSharedMemorySize, GEMM_SMEM);
        cudaFuncSetAttribute(attn_tf32, cudaFuncAttributeMaxDynamicSharedMemorySize, ATTN_SMEM);
        attr_done = true;
    }

    // prep: tf32-round x and weights
    const int NX4 = MTOT * DMODEL / 4;       // 1572864
    const int NW4 = DMODEL * DMODEL / 4;     // 147456
    prep_tf32<<<(NX4 + 255) / 256, 256>>>(x, xt, NX4);
    dim3 wprep_grid((NW4 + 255) / 256, 4);
    prep_tf32_w<<<wprep_grid, 256>>>(wq, wk, wv, wo, wt, NW4);

    const float qscale = 0.125f * 1.4426950408889634f;  // 1/sqrt(64) * log2(e)
    dim3 gemm_grid(DMODEL / TBN, MTOT / TBM);   // (12, 64)
    gemm_tf32<<<gemm_grid, 256, GEMM_SMEM>>>(xt, wt + 0 * DMODEL * DMODEL, nullptr, qp,
                                             MTOT, DMODEL, DMODEL, qscale, 1);
    gemm_tf32<<<gemm_grid, 256, GEMM_SMEM>>>(xt, wt + 1 * DMODEL * DMODEL, nullptr, kp,
                                             MTOT, DMODEL, DMODEL, 1.0f, 1);
    gemm_tf32<<<gemm_grid, 256, GEMM_SMEM>>>(xt, wt + 2 * DMODEL * DMODEL, nullptr, vp,
                                             MTOT, DMODEL, DMODEL, 1.0f, 1);

    dim3 attn_grid(SEQ / 128, NHEADS, BB);      // (32, 12, 2)
    attn_tf32<<<attn_grid, 128, ATTN_SMEM>>>(qp, kp, vp, cp);

    gemm_tf32<<<gemm_grid, 256, GEMM_SMEM>>>(cp, wt + 3 * DMODEL * DMODEL, bo, out,
                                             MTOT, DMODEL, DMODEL, 1.0f, 0);
}

// round 11
// speedup vs baseline: 5.1180x; 1.0315x over previous
#include <cuda_runtime.h>
#include <cstddef>
#include <cstdint>

#define BB 2
#define SEQ 4096
#define DMODEL 768
#define NHEADS 12
#define HDIM 64
#define MTOT (BB * SEQ)   // 8192

// Scratch (alloc-free rule: __device__ globals)
__device__ float g_xt[MTOT * DMODEL];            // x, tf32-rounded
__device__ float g_wt[4 * DMODEL * DMODEL];      // wq,wk,wv,wo tf32-rounded ([K,N] layout)
__device__ float g_q[MTOT * DMODEL];
__device__ float g_k[MTOT * DMODEL];
__device__ float g_v[MTOT * DMODEL];
__device__ float g_ctx[MTOT * DMODEL];

// single dynamic-smem symbol shared by all kernels
extern __shared__ unsigned dynsmem[];

// ---------------------------------------------------------------------------
// helpers
// ---------------------------------------------------------------------------
__device__ __forceinline__ unsigned f2tf(float f) {
    unsigned u;
    asm("cvt.rna.tf32.f32 %0, %1;" : "=r"(u) : "f"(f));
    return u;
}
__device__ __forceinline__ float ex2f(float x) {
    float y;
    asm("ex2.approx.f32 %0, %1;" : "=f"(y) : "f"(x));
    return y;
}
__device__ __forceinline__ void mma8(float c[4], const unsigned a[4], const unsigned b[2]) {
    asm volatile(
        "mma.sync.aligned.m16n8k8.row.col.f32.tf32.tf32.f32 "
        "{%0,%1,%2,%3}, {%4,%5,%6,%7}, {%8,%9}, {%0,%1,%2,%3};\n"
        : "+f"(c[0]), "+f"(c[1]), "+f"(c[2]), "+f"(c[3])
        : "r"(a[0]), "r"(a[1]), "r"(a[2]), "r"(a[3]), "r"(b[0]), "r"(b[1]));
}
__device__ __forceinline__ void cp16(uint32_t dst, const void* src) {
    asm volatile("cp.async.cg.shared.global [%0], [%1], 16;\n" :: "r"(dst), "l"(src));
}
#define CP_COMMIT() asm volatile("cp.async.commit_group;\n" ::: "memory")
#define CP_WAIT0()  asm volatile("cp.async.wait_group 0;\n" ::: "memory")

// ---------------------------------------------------------------------------
// prep kernels
// ---------------------------------------------------------------------------
__global__ void prep_tf32(const float* __restrict__ src, float* __restrict__ dst, int n4)
{
    int i = blockIdx.x * blockDim.x + threadIdx.x;
    if (i >= n4) return;
    float4 v = ((const float4*)src)[i];
    v.x = __uint_as_float(f2tf(v.x));
    v.y = __uint_as_float(f2tf(v.y));
    v.z = __uint_as_float(f2tf(v.z));
    v.w = __uint_as_float(f2tf(v.w));
    ((float4*)dst)[i] = v;
}

// 4 weight matrices in one launch (blockIdx.y selects matrix)
__global__ void prep_tf32_w(const float* __restrict__ w0, const float* __restrict__ w1,
                            const float* __restrict__ w2, const float* __restrict__ w3,
                            float* __restrict__ dst, int n4)
{
    int i = blockIdx.x * blockDim.x + threadIdx.x;
    if (i >= n4) return;
    const float* src = (blockIdx.y == 0) ? w0 : (blockIdx.y == 1) ? w1
                     : (blockIdx.y == 2) ? w2 : w3;
    float4 v = ((const float4*)src)[i];
    v.x = __uint_as_float(f2tf(v.x));
    v.y = __uint_as_float(f2tf(v.y));
    v.z = __uint_as_float(f2tf(v.z));
    v.w = __uint_as_float(f2tf(v.w));
    ((float4*)(dst + (size_t)blockIdx.y * DMODEL * DMODEL))[i] = v;
}

// ---------------------------------------------------------------------------
// tf32 GEMM: C = A@B (*outscale, +bias, optional tf32-round of output).
// Inputs already tf32 bit patterns. 128 thr, CTA tile 128x64x32, 4 warps,
// warp tile 32x64 (mi=2, ni=8): 24 LDS.32 per 16 mma (was 2.0/mma, now 1.5).
// smem 55KB -> 4 CTAs/SM (forced via launch_bounds reg cap).
// ---------------------------------------------------------------------------
#define TBM 128
#define TBN 64
#define TBK 32
#define ASTR 36
#define BSTR 72
#define GBUF (TBM * ASTR + TBK * BSTR)   // 6912 words per stage
#define GEMM_SMEM (2 * GBUF * 4)         // 55296 B

__global__ __launch_bounds__(128, 4) void gemm_tf32(
    const float* __restrict__ A, const float* __restrict__ B,
    const float* __restrict__ bias, float* __restrict__ C,
    int M, int N, int K, float outscale, int conv_out)
{
    unsigned* gsm = dynsmem;
    const uint32_t sbase = (uint32_t)__cvta_generic_to_shared(gsm);

    const int tid  = threadIdx.x;
    const int lane = tid & 31;
    const int w    = tid >> 5;       // 0..3
    const int g    = lane >> 2;
    const int t    = lane & 3;
    const int wm   = w * 32;         // warp owns rows [wm, wm+32), all 64 cols
    const int row0 = blockIdx.y * TBM;
    const int col0 = blockIdx.x * TBN;

    float c[2][8][4];
#pragma unroll
    for (int mi = 0; mi < 2; mi++)
#pragma unroll
        for (int ni = 0; ni < 8; ni++)
#pragma unroll
            for (int r = 0; r < 4; r++) c[mi][ni][r] = 0.0f;

    const int nk = K / TBK;

    // stage loader: A 1024 float4 (8/thread), B 512 float4 (4/thread)
    auto load_tile = [&](int k0, int buf) {
#pragma unroll
        for (int i = 0; i < 8; i++) {
            int id = tid + 128 * i, r = id >> 3, cc = id & 7;
            cp16(sbase + (uint32_t)(buf * GBUF + r * ASTR + cc * 4) * 4,
                 A + (size_t)(row0 + r) * K + k0 + cc * 4);
        }
#pragma unroll
        for (int i = 0; i < 4; i++) {
            int id = tid + 128 * i, r = id >> 4, cc = id & 15;
            cp16(sbase + (uint32_t)(buf * GBUF + TBM * ASTR + r * BSTR + cc * 4) * 4,
                 B + (size_t)(k0 + r) * N + col0 + cc * 4);
        }
    };

    load_tile(0, 0);
    CP_COMMIT();

    for (int kt = 0; kt < nk; kt++) {
        CP_WAIT0();
        __syncthreads();
        if (kt + 1 < nk) {
            load_tile((kt + 1) * TBK, (kt + 1) & 1);
            CP_COMMIT();
        }
        const unsigned* Asb = gsm + (kt & 1) * GBUF;
        const unsigned* Bsb = Asb + TBM * ASTR;
#pragma unroll
        for (int kp = 0; kp < 4; kp++) {
            unsigned af[2][4], bf[8][2];
#pragma unroll
            for (int mi = 0; mi < 2; mi++) {
                int r0 = (wm + mi * 16 + g) * ASTR + kp * 8 + t;
                int r1 = (wm + mi * 16 + g + 8) * ASTR + kp * 8 + t;
                af[mi][0] = Asb[r0];
                af[mi][1] = Asb[r1];
                af[mi][2] = Asb[r0 + 4];
                af[mi][3] = Asb[r1 + 4];
            }
#pragma unroll
            for (int ni = 0; ni < 8; ni++) {
                bf[ni][0] = Bsb[(kp * 8 + t) * BSTR + ni * 8 + g];
                bf[ni][1] = Bsb[(kp * 8 + t + 4) * BSTR + ni * 8 + g];
            }
#pragma unroll
            for (int mi = 0; mi < 2; mi++)
#pragma unroll
                for (int ni = 0; ni < 8; ni++)
                    mma8(c[mi][ni], af[mi], bf[ni]);
        }
        __syncthreads();
    }

    // epilogue
#pragma unroll
    for (int ni = 0; ni < 8; ni++) {
        int col = col0 + ni * 8 + 2 * t;
        float2 bv = make_float2(0.0f, 0.0f);
        if (bias) bv = *(const float2*)(bias + col);
#pragma unroll
        for (int mi = 0; mi < 2; mi++) {
            int r0 = row0 + wm + mi * 16 + g;
            float o00 = c[mi][ni][0] * outscale + bv.x;
            float o01 = c[mi][ni][1] * outscale + bv.y;
            float o10 = c[mi][ni][2] * outscale + bv.x;
            float o11 = c[mi][ni][3] * outscale + bv.y;
            if (conv_out) {
                o00 = __uint_as_float(f2tf(o00));
                o01 = __uint_as_float(f2tf(o01));
                o10 = __uint_as_float(f2tf(o10));
                o11 = __uint_as_float(f2tf(o11));
            }
            *(float2*)(C + (size_t)r0 * N + col) = make_float2(o00, o01);
            *(float2*)(C + (size_t)(r0 + 8) * N + col) = make_float2(o10, o11);
        }
    }
}

// ---------------------------------------------------------------------------
// Flash attention (proven R5 kernel, unchanged). Block = (b,h,128 Q rows),
// 128 thr, 2 CTAs/SM. Q fragments in registers; K/V cp.async double-buffered;
// P via register shuffles. tf32 inputs, Q pre-scaled by 0.125*log2(e).
// ---------------------------------------------------------------------------
#define QSTR 68
#define KSTR 68
#define VSTR 72
#define KWORDS (64 * KSTR)             // 4352
#define VWORDS (64 * VSTR)             // 4608
#define STG    (KWORDS + VWORDS)       // 8960 words per stage
#define ATTN_SMEM (2 * STG * 4)        // 71680 B

__global__ __launch_bounds__(128, 2) void attn_tf32(
    const float* __restrict__ Q, const float* __restrict__ K,
    const float* __restrict__ V, float* __restrict__ O)
{
    unsigned* smem = dynsmem;
    const uint32_t sbase = (uint32_t)__cvta_generic_to_shared(smem);

    const int tid  = threadIdx.x;
    const int lane = tid & 31;
    const int w    = tid >> 5;
    const int g    = lane >> 2;
    const int t    = lane & 3;
    const int qt   = (gridDim.x - 1) - blockIdx.x;   // big tiles first
    const int h    = blockIdx.y;
    const int b    = blockIdx.z;

    const float* Qptr = Q + ((size_t)(b * SEQ + qt * 128)) * DMODEL + h * HDIM;

#pragma unroll
    for (int i = 0; i < 16; i++) {
        int id = tid + 128 * i, r = id >> 4, cc = id & 15;
        cp16(sbase + (uint32_t)(r * QSTR + cc * 4) * 4, Qptr + (size_t)r * DMODEL + cc * 4);
    }
    CP_COMMIT();
    CP_WAIT0();
    __syncthreads();

    unsigned aq[8][2][4];
#pragma unroll
    for (int kp = 0; kp < 8; kp++)
#pragma unroll
        for (int mi = 0; mi < 2; mi++) {
            int r0 = (w * 32 + mi * 16 + g) * QSTR + kp * 8 + t;
            int r1 = r0 + 8 * QSTR;
            aq[kp][mi][0] = smem[r0];
            aq[kp][mi][1] = smem[r1];
            aq[kp][mi][2] = smem[r0 + 4];
            aq[kp][mi][3] = smem[r1 + 4];
        }
    __syncthreads();

    auto load_kv = [&](int kt, int buf) {
        const size_t kvb = ((size_t)(b * SEQ + kt * 64)) * DMODEL + h * HDIM;
#pragma unroll
        for (int i = 0; i < 8; i++) {
            int id = tid + 128 * i, r = id >> 4, cc = id & 15;
            cp16(sbase + (uint32_t)(buf * STG + r * KSTR + cc * 4) * 4,
                 K + kvb + (size_t)r * DMODEL + cc * 4);
            cp16(sbase + (uint32_t)(buf * STG + KWORDS + r * VSTR + cc * 4) * 4,
                 V + kvb + (size_t)r * DMODEL + cc * 4);
        }
    };
    load_kv(0, 0);
    CP_COMMIT();

    float co[2][8][4];
#pragma unroll
    for (int mi = 0; mi < 2; mi++)
#pragma unroll
        for (int ni = 0; ni < 8; ni++)
#pragma unroll
            for (int r = 0; r < 4; r++) co[mi][ni][r] = 0.0f;
    float mA[2] = {-1e30f, -1e30f}, mB[2] = {-1e30f, -1e30f};
    float lA[2] = {0.0f, 0.0f},     lB[2] = {0.0f, 0.0f};

    const int ntiles = 2 * qt + 2;
    const int srcA = (lane & ~3) | (t >> 1);
    const int srcB = srcA + 2;
    const bool hi = (t & 1);

    for (int kt = 0; kt < ntiles; kt++) {
        CP_WAIT0();
        __syncthreads();
        if (kt + 1 < ntiles) {
            load_kv(kt + 1, (kt + 1) & 1);
            CP_COMMIT();
        }
        const unsigned* Kb = smem + (kt & 1) * STG;
        const unsigned* Vb = Kb + KWORDS;

        float cs[2][8][4];
#pragma unroll
        for (int mi = 0; mi < 2; mi++)
#pragma unroll
            for (int ni = 0; ni < 8; ni++)
#pragma unroll
                for (int r = 0; r < 4; r++) cs[mi][ni][r] = 0.0f;
#pragma unroll
        for (int kp = 0; kp < 8; kp++) {
#pragma unroll
            for (int ni = 0; ni < 8; ni++) {
                unsigned bf[2];
                int rr = (ni * 8 + g) * KSTR + kp * 8 + t;
                bf[0] = Kb[rr];
                bf[1] = Kb[rr + 4];
                mma8(cs[0][ni], aq[kp][0], bf);
                mma8(cs[1][ni], aq[kp][1], bf);
            }
        }

        if (kt >= 2 * qt) {
            const int cb = kt * 64 + 2 * t;
            const int rb = qt * 128 + w * 32 + g;
#pragma unroll
            for (int mi = 0; mi < 2; mi++) {
                int r0 = rb + mi * 16;
#pragma unroll
                for (int ni = 0; ni < 8; ni++) {
                    int col = cb + ni * 8;
                    if (col > r0)         cs[mi][ni][0] = -1e30f;
                    if (col + 1 > r0)     cs[mi][ni][1] = -1e30f;
                    if (col > r0 + 8)     cs[mi][ni][2] = -1e30f;
                    if (col + 1 > r0 + 8) cs[mi][ni][3] = -1e30f;
                }
            }
        }

#pragma unroll
        for (int mi = 0; mi < 2; mi++) {
            float tm0 = -1e30f, tm1 = -1e30f;
#pragma unroll
            for (int ni = 0; ni < 8; ni++) {
                tm0 = fmaxf(tm0, fmaxf(cs[mi][ni][0], cs[mi][ni][1]));
                tm1 = fmaxf(tm1, fmaxf(cs[mi][ni][2], cs[mi][ni][3]));
            }
            tm0 = fmaxf(tm0, __shfl_xor_sync(0xffffffffu, tm0, 1));
            tm0 = fmaxf(tm0, __shfl_xor_sync(0xffffffffu, tm0, 2));
            tm1 = fmaxf(tm1, __shfl_xor_sync(0xffffffffu, tm1, 1));
            tm1 = fmaxf(tm1, __shfl_xor_sync(0xffffffffu, tm1, 2));

            float mn0 = fmaxf(mA[mi], tm0), mn1 = fmaxf(mB[mi], tm1);
            float al0 = ex2f(mA[mi] - mn0), al1 = ex2f(mB[mi] - mn1);
            float s0 = 0.0f, s1 = 0.0f;
#pragma unroll
            for (int ni = 0; ni < 8; ni++) {
                float p0 = ex2f(cs[mi][ni][0] - mn0); s0 += p0;
                float p1 = ex2f(cs[mi][ni][1] - mn0); s0 += p1;
                float p2 = ex2f(cs[mi][ni][2] - mn1); s1 += p2;
                float p3 = ex2f(cs[mi][ni][3] - mn1); s1 += p3;
                cs[mi][ni][0] = __uint_as_float(f2tf(p0));
                cs[mi][ni][1] = __uint_as_float(f2tf(p1));
                cs[mi][ni][2] = __uint_as_float(f2tf(p2));
                cs[mi][ni][3] = __uint_as_float(f2tf(p3));
            }
            s0 += __shfl_xor_sync(0xffffffffu, s0, 1);
            s0 += __shfl_xor_sync(0xffffffffu, s0, 2);
            s1 += __shfl_xor_sync(0xffffffffu, s1, 1);
            s1 += __shfl_xor_sync(0xffffffffu, s1, 2);
            lA[mi] = lA[mi] * al0 + s0;
            lB[mi] = lB[mi] * al1 + s1;
            mA[mi] = mn0; mB[mi] = mn1;
#pragma unroll
            for (int ni = 0; ni < 8; ni++) {
                co[mi][ni][0] *= al0; co[mi][ni][1] *= al0;
                co[mi][ni][2] *= al1; co[mi][ni][3] *= al1;
            }
        }

#pragma unroll
        for (int kp = 0; kp < 8; kp++) {
            unsigned ap[2][4];
#pragma unroll
            for (int mi = 0; mi < 2; mi++) {
                float x0 = __shfl_sync(0xffffffffu, cs[mi][kp][0], srcA);
                float x1 = __shfl_sync(0xffffffffu, cs[mi][kp][1], srcA);
                float y0 = __shfl_sync(0xffffffffu, cs[mi][kp][2], srcA);
                float y1 = __shfl_sync(0xffffffffu, cs[mi][kp][3], srcA);
                float z0 = __shfl_sync(0xffffffffu, cs[mi][kp][0], srcB);
                float z1 = __shfl_sync(0xffffffffu, cs[mi][kp][1], srcB);
                float u0 = __shfl_sync(0xffffffffu, cs[mi][kp][2], srcB);
                float u1 = __shfl_sync(0xffffffffu, cs[mi][kp][3], srcB);
                ap[mi][0] = __float_as_uint(hi ? x1 : x0);
                ap[mi][1] = __float_as_uint(hi ? y1 : y0);
                ap[mi][2] = __float_as_uint(hi ? z1 : z0);
                ap[mi][3] = __float_as_uint(hi ? u1 : u0);
            }
#pragma unroll
            for (int ni = 0; ni < 8; ni++) {
                unsigned bf[2];
                bf[0] = Vb[(kp * 8 + t) * VSTR + ni * 8 + g];
                bf[1] = Vb[(kp * 8 + t + 4) * VSTR + ni * 8 + g];
                mma8(co[0][ni], ap[0], bf);
                mma8(co[1][ni], ap[1], bf);
            }
        }
    }

#pragma unroll
    for (int mi = 0; mi < 2; mi++) {
        const float i0 = 1.0f / lA[mi], i1 = 1.0f / lB[mi];
        size_t rbase = ((size_t)(b * SEQ + qt * 128 + w * 32 + mi * 16 + g)) * DMODEL + h * HDIM;
#pragma unroll
        for (int ni = 0; ni < 8; ni++) {
            size_t r0 = rbase + ni * 8 + 2 * t;
            *(float2*)(O + r0) = make_float2(
                __uint_as_float(f2tf(co[mi][ni][0] * i0)),
                __uint_as_float(f2tf(co[mi][ni][1] * i0)));
            *(float2*)(O + r0 + (size_t)8 * DMODEL) = make_float2(
                __uint_as_float(f2tf(co[mi][ni][2] * i1)),
                __uint_as_float(f2tf(co[mi][ni][3] * i1)));
        }
    }
}

// ---------------------------------------------------------------------------
extern "C" void kernel_launch(void* const* d_in, const int* in_sizes, int n_in,
                              void* d_out, int out_size)
{
    (void)in_sizes; (void)n_in; (void)out_size;
    const float* x  = (const float*)d_in[0];
    const float* wq = (const float*)d_in[1];
    const float* wk = (const float*)d_in[2];
    const float* wv = (const float*)d_in[3];
    const float* wo = (const float*)d_in[4];
    const float* bo = (const float*)d_in[5];
    float* out = (float*)d_out;

    float *xt, *wt, *qp, *kp, *vp, *cp;
    cudaGetSymbolAddress((void**)&xt, g_xt);
    cudaGetSymbolAddress((void**)&wt, g_wt);
    cudaGetSymbolAddress((void**)&qp, g_q);
    cudaGetSymbolAddress((void**)&kp, g_k);
    cudaGetSymbolAddress((void**)&vp, g_v);
    cudaGetSymbolAddress((void**)&cp, g_ctx);

    static bool attr_done = false;
    if (!attr_done) {
        cudaFuncSetAttribute(gemm_tf32, cudaFuncAttributeMaxDynamicSharedMemorySize, GEMM_SMEM);
        cudaFuncSetAttribute(attn_tf32, cudaFuncAttributeMaxDynamicSharedMemorySize, ATTN_SMEM);
        attr_done = true;
    }

    // prep: tf32-round x and weights
    const int NX4 = MTOT * DMODEL / 4;       // 1572864
    const int NW4 = DMODEL * DMODEL / 4;     // 147456
    prep_tf32<<<(NX4 + 255) / 256, 256>>>(x, xt, NX4);
    dim3 wprep_grid((NW4 + 255) / 256, 4);
    prep_tf32_w<<<wprep_grid, 256>>>(wq, wk, wv, wo, wt, NW4);

    const float qscale = 0.125f * 1.4426950408889634f;  // 1/sqrt(64) * log2(e)
    dim3 gemm_grid(DMODEL / TBN, MTOT / TBM);   // (12, 64)
    gemm_tf32<<<gemm_grid, 128, GEMM_SMEM>>>(xt, wt + 0 * DMODEL * DMODEL, nullptr, qp,
                                             MTOT, DMODEL, DMODEL, qscale, 1);
    gemm_tf32<<<gemm_grid, 128, GEMM_SMEM>>>(xt, wt + 1 * DMODEL * DMODEL, nullptr, kp,
                                             MTOT, DMODEL, DMODEL, 1.0f, 1);
    gemm_tf32<<<gemm_grid, 128, GEMM_SMEM>>>(xt, wt + 2 * DMODEL * DMODEL, nullptr, vp,
                                             MTOT, DMODEL, DMODEL, 1.0f, 1);

    dim3 attn_grid(SEQ / 128, NHEADS, BB);      // (32, 12, 2)
    attn_tf32<<<attn_grid, 128, ATTN_SMEM>>>(qp, kp, vp, cp);

    gemm_tf32<<<gemm_grid, 128, GEMM_SMEM>>>(cp, wt + 3 * DMODEL * DMODEL, bo, out,
                                             MTOT, DMODEL, DMODEL, 1.0f, 0);
}